// round 8
// baseline (speedup 1.0000x reference)
#include <cuda_runtime.h>
#include <stdint.h>

// GINGCN forward:
//   deg[c]  = # edges with col==c  (in-degree over col)
//   dis[i]  = deg[i]>0 ? rsqrt(deg[i]) : 0
//   out[r]  = (1+eps)*x[r] + sum_{e: row[e]==r} dis[r]*dis[col[e]] * x[col[e]]
//
// Strategy: bucket-CSR gather, 4 launches.
//   K0 zero counters + overflow count + dtype detect (fused)
//   K1 ONE edge pass (2 edges/thread, vectorized loads): atomicAdd deg[col];
//      append col to bucket[row]. Overflow -> global (r,c) list.
//   K2 gather: 1 warp/node, lane owns 4 features. Per 32-entry chunk each
//      lane loads its bucket col + deg[col], computes norm; chunk length is
//      rounded up to a multiple of 8 (padded lanes have norm=0) so the inner
//      loop is a fixed fully-unrolled 8-wide body -> 8 independent LDG.128
//      in flight, no remainder branches.
//   K3 drain overflow list with float atomics (no-op when empty).

#define N_MAX   100000
#define D       128
#define D4      (D / 4)        // 32 float4 per row
#define CAP     64
#define OVF_MAX 2000000

__device__ int  g_deg[N_MAX];                  // in-degree (col counts)
__device__ int  g_cnt[N_MAX];                  // per-row bucket fill counts
__device__ int  g_bkt[(size_t)N_MAX * CAP];    // bucket: col only
__device__ int  g_is64;                        // edge dtype flag
__device__ int  g_ovf_n;                       // overflow entry count
__device__ int2 g_ovf[OVF_MAX];                // overflow: {row, col}

// ---------------------------------------------------------------- K0: zero+detect
// dtype sniff: int64 little-endian values < 2^31 -> every odd int32 word is 0.
// 64 odd words all zero from genuine int32 node-id data is ~impossible.
__global__ void k_zero(const void* ei, int n) {
    int i = blockIdx.x * blockDim.x + threadIdx.x;
    if (i < n) { g_deg[i] = 0; g_cnt[i] = 0; }
    if (i == 0) {
        g_ovf_n = 0;
        const int* p = (const int*)ei;
        int nz = 0;
        #pragma unroll
        for (int k = 0; k < 64; k++) nz |= p[2 * k + 1];
        g_is64 = (nz == 0) ? 1 : 0;
    }
}

// ---------------------------------------------------------------- K1: count+fill
// One pass, 2 edges per thread with vector loads. Degree count and bucket
// append are independent (no deg reads here).
__device__ __forceinline__ void build_edge(int r, int c) {
    atomicAdd(&g_deg[c], 1);
    int slot = atomicAdd(&g_cnt[r], 1);
    if (slot < CAP) {
        g_bkt[(size_t)r * CAP + slot] = c;
    } else {
        int o = atomicAdd(&g_ovf_n, 1);
        if (o < OVF_MAX) g_ovf[o] = make_int2(r, c);
    }
}

__global__ void k_build(const void* ei, int E) {
    int t  = blockIdx.x * blockDim.x + threadIdx.x;
    int e0 = t * 2;
    if (e0 >= E) return;
    int is64 = g_is64;
    int r0, c0, r1 = -1, c1 = -1;
    bool two = (e0 + 1 < E);
    if (is64) {
        const long long* p = (const long long*)ei;
        if (two && ((e0 & 1) == 0)) {
            longlong2 rr = ((const longlong2*)(p))[e0 >> 1];
            longlong2 cc = ((const longlong2*)(p + E))[e0 >> 1];
            r0 = (int)rr.x; r1 = (int)rr.y;
            c0 = (int)cc.x; c1 = (int)cc.y;
        } else {
            r0 = (int)p[e0]; c0 = (int)p[(size_t)E + e0];
            if (two) { r1 = (int)p[e0 + 1]; c1 = (int)p[(size_t)E + e0 + 1]; }
        }
    } else {
        const int* p = (const int*)ei;
        if (two && ((e0 & 1) == 0)) {
            int2 rr = ((const int2*)(p))[e0 >> 1];
            int2 cc = ((const int2*)(p + E))[e0 >> 1];
            r0 = rr.x; r1 = rr.y;
            c0 = cc.x; c1 = cc.y;
        } else {
            r0 = p[e0]; c0 = p[(size_t)E + e0];
            if (two) { r1 = p[e0 + 1]; c1 = p[(size_t)E + e0 + 1]; }
        }
    }
    build_edge(r0, c0);
    if (two) build_edge(r1, c1);
}

// ---------------------------------------------------------------- K2: gather
// out[w] = (1+eps)*x[w] + dis_w * sum rsqrt(deg[c]) * x[c]
// deg[c] >= 1 guaranteed for bucketed edges (the edge itself counted).
__global__ void __launch_bounds__(256)
k_gather(const float4* __restrict__ x4, float4* __restrict__ o4,
         const float* __restrict__ eps, int n) {
    int w    = (blockIdx.x * blockDim.x + threadIdx.x) >> 5;
    int lane = threadIdx.x & 31;
    if (w >= n) return;

    int cnt = g_cnt[w];
    if (cnt > CAP) cnt = CAP;

    float  s  = 1.0f + eps[0];
    float4 xv = x4[(size_t)w * D4 + lane];
    float4 acc;
    acc.x = s * xv.x; acc.y = s * xv.y; acc.z = s * xv.z; acc.w = s * xv.w;

    int   dw    = g_deg[w];
    float dis_w = (dw > 0) ? rsqrtf((float)dw) : 0.0f;

    size_t base = (size_t)w * CAP;
    for (int j0 = 0; j0 < cnt; j0 += 32) {
        int   mycol = 0;
        float mynrm = 0.0f;
        int idx = j0 + lane;
        if (idx < cnt) {
            mycol = g_bkt[base + idx];
            mynrm = dis_w * rsqrtf((float)g_deg[mycol]);
        }
        // Round chunk length up to a multiple of 8: padded lanes carry
        // norm=0 so their contribution is exactly zero (x[0] gather, L1-hot).
        int m = min(32, cnt - j0);
        m = (m + 7) & ~7;

        for (int j = 0; j < m; j += 8) {
            #pragma unroll
            for (int u = 0; u < 8; u++) {
                int   c  = __shfl_sync(0xffffffffu, mycol, j + u);
                float nm = __shfl_sync(0xffffffffu, mynrm, j + u);
                float4 v = x4[(size_t)c * D4 + lane];
                acc.x += nm * v.x;
                acc.y += nm * v.y;
                acc.z += nm * v.z;
                acc.w += nm * v.w;
            }
        }
    }
    o4[(size_t)w * D4 + lane] = acc;
}

// ---------------------------------------------------------------- K3: overflow
// Persistent drain of overflow list into out (no-op for this distribution).
// deg is final here; norm computed from deg directly.
__global__ void k_ovf(const float4* __restrict__ x4, float* out) {
    int nov = g_ovf_n;
    if (nov > OVF_MAX) nov = OVF_MAX;
    int warp  = (blockIdx.x * blockDim.x + threadIdx.x) >> 5;
    int nwarp = (gridDim.x * blockDim.x) >> 5;
    int lane  = threadIdx.x & 31;
    for (int i = warp; i < nov; i += nwarp) {
        int2 t = g_ovf[i];
        int dr = g_deg[t.x];
        int dc = g_deg[t.y];
        float nm = (dr > 0 && dc > 0) ? rsqrtf((float)dr * (float)dc) : 0.0f;
        float4 v = x4[(size_t)t.y * D4 + lane];
        float* o = out + (size_t)t.x * D + lane * 4;
        atomicAdd(o + 0, nm * v.x);
        atomicAdd(o + 1, nm * v.y);
        atomicAdd(o + 2, nm * v.z);
        atomicAdd(o + 3, nm * v.w);
    }
}

// ---------------------------------------------------------------- launch
extern "C" void kernel_launch(void* const* d_in, const int* in_sizes, int n_in,
                              void* d_out, int out_size) {
    const float* x   = (const float*)d_in[0];
    const float* eps = (const float*)d_in[1];
    const void*  ei  = d_in[2];
    float*       out = (float*)d_out;

    int n = in_sizes[0] / D;       // 100000
    int E = in_sizes[2] / 2;       // 1600000
    int nt = (E + 1) / 2;          // build threads (2 edges each)

    const int T = 256;
    k_zero  <<<(n + T - 1) / T, T>>>(ei, n);
    k_build <<<(nt + T - 1) / T, T>>>(ei, E);
    k_gather<<<(n * 32 + T - 1) / T, T>>>((const float4*)x, (float4*)out, eps, n);
    k_ovf   <<<32, T>>>((const float4*)x, out);
}